// round 1
// baseline (speedup 1.0000x reference)
#include <cuda_runtime.h>
#include <cuda_bf16.h>

// actions: [B=4096, T=256, A=64] fp32
// out[b,0,a]   = x[b,0,a]
// out[b,t,a]   = out[b,t-1,a] + clip(x[b,t,a] - x[b,t-1,a], -0.5, 0.5)
//
// One thread per (b, a-quad) lane: 16 float4 lanes per (b,t) row of 64 floats.
// Loads at each t are address-independent of the accumulator -> unrolled loop
// keeps ~4 loads in flight per thread; warp-coalesced 128B sectors.

#define TT 256          // time steps
#define ROW4 16         // float4 lanes per row (64 floats / 4)
#define MAXD 0.5f

__global__ __launch_bounds__(128) void smooth_scan_kernel(
    const float4* __restrict__ in, float4* __restrict__ out)
{
    const unsigned idx = blockIdx.x * blockDim.x + threadIdx.x;  // 0..65535
    const unsigned b  = idx >> 4;     // batch
    const unsigned a4 = idx & 15;     // float4 lane within row

    size_t base = (size_t)b * (TT * ROW4) + a4;

    float4 prev = in[base];   // raw x[t-1]
    float4 acc  = prev;       // reconstructed out[t-1]
    out[base] = acc;

    #pragma unroll 8
    for (int t = 1; t < TT; ++t) {
        float4 x = in[base + (size_t)t * ROW4];

        float dx = fminf(fmaxf(x.x - prev.x, -MAXD), MAXD);
        float dy = fminf(fmaxf(x.y - prev.y, -MAXD), MAXD);
        float dz = fminf(fmaxf(x.z - prev.z, -MAXD), MAXD);
        float dw = fminf(fmaxf(x.w - prev.w, -MAXD), MAXD);

        acc.x += dx; acc.y += dy; acc.z += dz; acc.w += dw;
        prev = x;

        out[base + (size_t)t * ROW4] = acc;
    }
}

extern "C" void kernel_launch(void* const* d_in, const int* in_sizes, int n_in,
                              void* d_out, int out_size)
{
    const float4* in  = (const float4*)d_in[0];
    float4*       out = (float4*)d_out;

    // total lanes = B * 16 = 4096 * 16 = 65536
    const int threads = 128;
    const int blocks  = (4096 * ROW4) / threads;  // 512
    smooth_scan_kernel<<<blocks, threads>>>(in, out);
}